// round 1
// baseline (speedup 1.0000x reference)
#include <cuda_runtime.h>
#include <cuda_bf16.h>
#include <math.h>
#include <stdint.h>

#define K_COMP 64
#define DDIM   256
#define MU_PAD 264   // bf16 elems per smem row: 132 words -> conflict-free B loads

__device__ __align__(16) __nv_bfloat16 g_mu[K_COMP * DDIM];
__device__ float g_kappa[K_COMP];
__device__ float g_logC[K_COMP];
__device__ float g_la[K_COMP];
__device__ float g_C2[K_COMP];

// ---------------- prep: K=64 per-component constants, double precision ----------------
__global__ void prep_kernel(const float* __restrict__ alpha_logit,
                            const float* __restrict__ mu_unnorm,
                            const float* __restrict__ log_kappa) {
    int k = threadIdx.x;
    if (k >= K_COMP) return;

    // log_softmax(alpha_logit)
    double amax = -1e300;
    for (int i = 0; i < K_COMP; i++) amax = fmax(amax, (double)alpha_logit[i]);
    double asum = 0.0;
    for (int i = 0; i < K_COMP; i++) asum += exp((double)alpha_logit[i] - amax);
    double la = (double)alpha_logit[k] - (amax + log(asum));

    // normalize mu row -> bf16
    double nrm = 0.0;
    for (int d = 0; d < DDIM; d++) { double v = (double)mu_unnorm[k * DDIM + d]; nrm += v * v; }
    nrm = sqrt(nrm);
    if (nrm < 1e-12) nrm = 1e-12;
    for (int d = 0; d < DDIM; d++)
        g_mu[k * DDIM + d] = __float2bfloat16((float)((double)mu_unnorm[k * DDIM + d] / nrm));

    double kappa = exp((double)log_kappa[k]) + 1e-6;
    double s   = 0.5 * (double)DDIM - 1.0;
    double lk2 = log(kappa * 0.5);

    // log I_s(kappa), 64-term ascending series (two-pass logsumexp)
    double tmax = -1e300;
    for (int m = 0; m < 64; m++) {
        double t = (2.0 * m + s) * lk2 - lgamma((double)m + 1.0) - lgamma((double)m + s + 1.0);
        tmax = fmax(tmax, t);
    }
    double tsum = 0.0;
    for (int m = 0; m < 64; m++) {
        double t = (2.0 * m + s) * lk2 - lgamma((double)m + 1.0) - lgamma((double)m + s + 1.0);
        tsum += exp(t - tmax);
    }
    double lbi  = tmax + log(tsum);
    double logC = (double)DDIM * (-0.5 * log(2.0 * M_PI)) + s * log(kappa) - lbi;

    g_kappa[k] = (float)kappa;
    g_logC[k]  = (float)logC;
    g_la[k]    = (float)la;
    g_C2[k]    = (float)(logC + la);
}

// ---------------- fast exp: FFMA-only (avoids MUFU bottleneck at 16.8M calls) ----------
__device__ __forceinline__ float fexp(float x) {
    // valid for x in [-87, ~0.5]; callers pass y - rowmax <= ~1ulp above 0
    x = fmaxf(x, -87.0f);
    float z = x * 1.4426950408889634f;         // x * log2(e)
    float t = z + 12582912.0f;                 // round-to-nearest via magic number
    float fi = t - 12582912.0f;                // integer part as float
    float f = z - fi;                          // frac in [-0.5, 0.5]
    int  i  = __float_as_int(t) - 0x4B400000;  // = round(z)
    // 2^f, degree-5 Taylor (max rel err ~2.4e-6 on [-0.5,0.5])
    float p = 1.3333558e-3f;
    p = fmaf(p, f, 9.6181291e-3f);
    p = fmaf(p, f, 5.5504109e-2f);
    p = fmaf(p, f, 2.4022651e-1f);
    p = fmaf(p, f, 6.9314718e-1f);
    p = fmaf(p, f, 1.0f);
    return __int_as_float(__float_as_int(p) + (i << 23));  // * 2^i
}

__device__ __forceinline__ uint32_t f22bf(float2 v) {
    __nv_bfloat162 b = __float22bfloat162_rn(v);   // .x -> low half
    return *reinterpret_cast<uint32_t*>(&b);
}

// ---------------- main fused kernel: bf16 MMA + epilogue + logsumexp ------------------
__global__ void __launch_bounds__(256)
vmf_main(const float* __restrict__ x,
         float* __restrict__ out_llh,
         float* __restrict__ out_lp,
         int N) {
    __shared__ __align__(16) __nv_bfloat16 smu[K_COMP][MU_PAD];
    __shared__ float s_kappa[K_COMP], s_logC[K_COMP], s_la[K_COMP], s_C2[K_COMP];

    int tid = threadIdx.x;

    // stage mu (bf16) into padded smem
    const uint32_t* gmu32 = reinterpret_cast<const uint32_t*>(g_mu);
    for (int idx = tid; idx < K_COMP * (DDIM / 2); idx += 256) {
        int kk = idx >> 7;        // / (DDIM/2)
        int dp = idx & 127;
        reinterpret_cast<uint32_t*>(&smu[kk][0])[dp] = gmu32[idx];
    }
    if (tid < K_COMP) {
        s_kappa[tid] = g_kappa[tid];
        s_logC[tid]  = g_logC[tid];
        s_la[tid]    = g_la[tid];
        s_C2[tid]    = g_C2[tid];
    }
    __syncthreads();

    int warp = tid >> 5, lane = tid & 31;
    int row0 = blockIdx.x * 128 + warp * 16;
    if (row0 >= N) return;

    int r  = lane >> 2;        // 0..7
    int cq = (lane & 3) * 2;   // 0,2,4,6

    const float* pa0 = x + (size_t)(row0 + r)     * DDIM + cq;
    const float* pa1 = x + (size_t)(row0 + r + 8) * DDIM + cq;

    float acc[8][4];
#pragma unroll
    for (int t = 0; t < 8; t++) { acc[t][0] = acc[t][1] = acc[t][2] = acc[t][3] = 0.0f; }

    // prime double buffer
    float2 a00 = __ldcs(reinterpret_cast<const float2*>(pa0));
    float2 a10 = __ldcs(reinterpret_cast<const float2*>(pa1));
    float2 a01 = __ldcs(reinterpret_cast<const float2*>(pa0 + 8));
    float2 a11 = __ldcs(reinterpret_cast<const float2*>(pa1 + 8));

#pragma unroll
    for (int kk = 0; kk < 16; kk++) {
        float2 n00 = a00, n10 = a10, n01 = a01, n11 = a11;
        if (kk < 15) {
            int off = (kk + 1) * 16;
            n00 = __ldcs(reinterpret_cast<const float2*>(pa0 + off));
            n10 = __ldcs(reinterpret_cast<const float2*>(pa1 + off));
            n01 = __ldcs(reinterpret_cast<const float2*>(pa0 + off + 8));
            n11 = __ldcs(reinterpret_cast<const float2*>(pa1 + off + 8));
        }
        uint32_t fa0 = f22bf(a00), fa1 = f22bf(a10), fa2 = f22bf(a01), fa3 = f22bf(a11);
        int dbase = kk * 16 + cq;
#pragma unroll
        for (int t = 0; t < 8; t++) {
            int n = t * 8 + r;
            uint32_t b0 = *reinterpret_cast<const uint32_t*>(&smu[n][dbase]);
            uint32_t b1 = *reinterpret_cast<const uint32_t*>(&smu[n][dbase + 8]);
            asm volatile(
                "mma.sync.aligned.m16n8k16.row.col.f32.bf16.bf16.f32 "
                "{%0,%1,%2,%3}, {%4,%5,%6,%7}, {%8,%9}, {%0,%1,%2,%3};\n"
                : "+f"(acc[t][0]), "+f"(acc[t][1]), "+f"(acc[t][2]), "+f"(acc[t][3])
                : "r"(fa0), "r"(fa1), "r"(fa2), "r"(fa3), "r"(b0), "r"(b1));
        }
        a00 = n00; a10 = n10; a01 = n01; a11 = n11;
    }

    // ---- epilogue: log_prob = kappa*dot + logC ; per-row logsumexp(log_prob + la) ----
    int gr0 = row0 + r, gr1 = gr0 + 8;
    float2* lp0 = reinterpret_cast<float2*>(out_lp + (size_t)gr0 * K_COMP);
    float2* lp1 = reinterpret_cast<float2*>(out_lp + (size_t)gr1 * K_COMP);

    float m0 = -1e30f, m1 = -1e30f;
#pragma unroll
    for (int t = 0; t < 8; t++) {
        int c = t * 8 + cq;
        float k0 = s_kappa[c], k1 = s_kappa[c + 1];
        float lc0 = s_logC[c], lc1 = s_logC[c + 1];
        float la0 = s_la[c],   la1 = s_la[c + 1];
        float lp00 = fmaf(k0, acc[t][0], lc0);
        float lp01 = fmaf(k1, acc[t][1], lc1);
        float lp10 = fmaf(k0, acc[t][2], lc0);
        float lp11 = fmaf(k1, acc[t][3], lc1);
        __stcs(lp0 + (c >> 1), make_float2(lp00, lp01));
        __stcs(lp1 + (c >> 1), make_float2(lp10, lp11));
        m0 = fmaxf(m0, fmaxf(lp00 + la0, lp01 + la1));
        m1 = fmaxf(m1, fmaxf(lp10 + la0, lp11 + la1));
    }
    m0 = fmaxf(m0, __shfl_xor_sync(0xffffffffu, m0, 1));
    m0 = fmaxf(m0, __shfl_xor_sync(0xffffffffu, m0, 2));
    m1 = fmaxf(m1, __shfl_xor_sync(0xffffffffu, m1, 1));
    m1 = fmaxf(m1, __shfl_xor_sync(0xffffffffu, m1, 2));

    float s0 = 0.0f, s1 = 0.0f;
#pragma unroll
    for (int t = 0; t < 8; t++) {
        int c = t * 8 + cq;
        float k0 = s_kappa[c], k1 = s_kappa[c + 1];
        float c20 = s_C2[c],   c21 = s_C2[c + 1];
        s0 += fexp(fmaf(k0, acc[t][0], c20) - m0);
        s0 += fexp(fmaf(k1, acc[t][1], c21) - m0);
        s1 += fexp(fmaf(k0, acc[t][2], c20) - m1);
        s1 += fexp(fmaf(k1, acc[t][3], c21) - m1);
    }
    s0 += __shfl_xor_sync(0xffffffffu, s0, 1);
    s0 += __shfl_xor_sync(0xffffffffu, s0, 2);
    s1 += __shfl_xor_sync(0xffffffffu, s1, 1);
    s1 += __shfl_xor_sync(0xffffffffu, s1, 2);

    if ((lane & 3) == 0) {
        out_llh[gr0] = m0 + __logf(s0);
        out_llh[gr1] = m1 + __logf(s1);
    }
}

// ---------------- launch -----------------------------------------------------------
extern "C" void kernel_launch(void* const* d_in, const int* in_sizes, int n_in,
                              void* d_out, int out_size) {
    const float* x           = (const float*)d_in[0];
    const float* alpha_logit = (const float*)d_in[1];
    const float* mu_unnorm   = (const float*)d_in[2];
    const float* log_kappa   = (const float*)d_in[3];

    int K = in_sizes[1];            // 64
    int D = in_sizes[2] / K;        // 256
    int N = in_sizes[0] / D;        // 262144
    (void)K; (void)n_in; (void)out_size;

    float* out = (float*)d_out;
    float* llh = out;               // (N,)
    float* lp  = out + (size_t)N;   // (N, K) row-major

    prep_kernel<<<1, K_COMP>>>(alpha_logit, mu_unnorm, log_kappa);
    vmf_main<<<N / 128, 256>>>(x, llh, lp, N);
}

// round 2
// speedup vs baseline: 6.6769x; 6.6769x over previous
#include <cuda_runtime.h>
#include <cuda_bf16.h>
#include <math.h>
#include <stdint.h>

#define K_COMP 64
#define DDIM   256
#define MU_PAD 264   // bf16 elems per smem row -> conflict-free B loads

__device__ __align__(16) __nv_bfloat16 g_mu[K_COMP * DDIM];
__device__ float g_kappa[K_COMP];
__device__ float g_logC[K_COMP];
__device__ float g_la[K_COMP];
__device__ float g_C2[K_COMP];

// ---------------- prep: parallel fp32 (reference is fp32 jax; fp64 lgamma was 590us!) --
__global__ void prep_fast(const float* __restrict__ alpha_logit,
                          const float* __restrict__ mu_unnorm,
                          const float* __restrict__ log_kappa) {
    __shared__ float cm[K_COMP];   // gammaln(m+1)+gammaln(m+s+1): independent of k!
    __shared__ float sa[K_COMP];
    int tid = threadIdx.x, warp = tid >> 5, lane = tid & 31;
    const float s = 0.5f * (float)DDIM - 1.0f;   // 127

    if (tid < K_COMP) {
        cm[tid] = lgammaf((float)tid + 1.0f) + lgammaf((float)tid + s + 1.0f);
        sa[tid] = alpha_logit[tid];
    }
    __syncthreads();

    // mu normalization: warp w handles rows w*8 .. w*8+7, lane-parallel over D
#pragma unroll
    for (int rr = 0; rr < 8; rr++) {
        int k = warp * 8 + rr;
        const float4* p = reinterpret_cast<const float4*>(mu_unnorm + (size_t)k * DDIM);
        float4 v1 = p[lane * 2], v2 = p[lane * 2 + 1];
        float sum = v1.x*v1.x + v1.y*v1.y + v1.z*v1.z + v1.w*v1.w
                  + v2.x*v2.x + v2.y*v2.y + v2.z*v2.z + v2.w*v2.w;
#pragma unroll
        for (int off = 16; off > 0; off >>= 1)
            sum += __shfl_xor_sync(0xffffffffu, sum, off);
        float nrm = sqrtf(sum);
        nrm = fmaxf(nrm, 1e-12f);
        float inv = 1.0f / nrm;
        __nv_bfloat162* dst = reinterpret_cast<__nv_bfloat162*>(g_mu + (size_t)k * DDIM);
        dst[lane * 4 + 0] = __float22bfloat162_rn(make_float2(v1.x * inv, v1.y * inv));
        dst[lane * 4 + 1] = __float22bfloat162_rn(make_float2(v1.z * inv, v1.w * inv));
        dst[lane * 4 + 2] = __float22bfloat162_rn(make_float2(v2.x * inv, v2.y * inv));
        dst[lane * 4 + 3] = __float22bfloat162_rn(make_float2(v2.z * inv, v2.w * inv));
    }

    if (tid < K_COMP) {
        int k = tid;
        // log_softmax
        float amax = -1e30f;
        for (int i = 0; i < K_COMP; i++) amax = fmaxf(amax, sa[i]);
        float asum = 0.0f;
        for (int i = 0; i < K_COMP; i++) asum += expf(sa[i] - amax);
        float la = sa[k] - (amax + logf(asum));

        float kappa = expf(log_kappa[k]) + 1e-6f;
        float lk2   = logf(0.5f * kappa);

        // log I_s(kappa): terms = (2m+s)*lk2 - cm[m]
        float tmax = -1e30f;
        for (int m = 0; m < 64; m++)
            tmax = fmaxf(tmax, fmaf(2.0f * m + s, lk2, -cm[m]));
        float tsum = 0.0f;
        for (int m = 0; m < 64; m++)
            tsum += expf(fmaf(2.0f * m + s, lk2, -cm[m]) - tmax);
        float lbi  = tmax + logf(tsum);
        float logC = (float)DDIM * (-0.91893853320467274f) + s * logf(kappa) - lbi;

        g_kappa[k] = kappa;
        g_logC[k]  = logC;
        g_la[k]    = la;
        g_C2[k]    = logC + la;
    }
}

// ---------------- fast exp: FFMA-only --------------------------------------------------
__device__ __forceinline__ float fexp(float x) {
    x = fmaxf(x, -87.0f);
    float z = x * 1.4426950408889634f;
    float t = z + 12582912.0f;
    float fi = t - 12582912.0f;
    float f = z - fi;
    int  i  = __float_as_int(t) - 0x4B400000;
    float p = 1.3333558e-3f;
    p = fmaf(p, f, 9.6181291e-3f);
    p = fmaf(p, f, 5.5504109e-2f);
    p = fmaf(p, f, 2.4022651e-1f);
    p = fmaf(p, f, 6.9314718e-1f);
    p = fmaf(p, f, 1.0f);
    return __int_as_float(__float_as_int(p) + (i << 23));
}

__device__ __forceinline__ uint32_t f22bf(float2 v) {
    __nv_bfloat162 b = __float22bfloat162_rn(v);
    return *reinterpret_cast<uint32_t*>(&b);
}

// ---------------- main fused kernel: 32 rows/warp, 2x m16n8k16 tiles share B ----------
__global__ void __launch_bounds__(256, 2)
vmf_main(const float* __restrict__ x,
         float* __restrict__ out_llh,
         float* __restrict__ out_lp,
         int N) {
    __shared__ __align__(16) __nv_bfloat16 smu[K_COMP][MU_PAD];
    __shared__ float s_kappa[K_COMP], s_logC[K_COMP], s_la[K_COMP], s_C2[K_COMP];

    int tid = threadIdx.x;

    const uint32_t* gmu32 = reinterpret_cast<const uint32_t*>(g_mu);
    for (int idx = tid; idx < K_COMP * (DDIM / 2); idx += 256) {
        int kk = idx >> 7;
        int dp = idx & 127;
        reinterpret_cast<uint32_t*>(&smu[kk][0])[dp] = gmu32[idx];
    }
    if (tid < K_COMP) {
        s_kappa[tid] = g_kappa[tid];
        s_logC[tid]  = g_logC[tid];
        s_la[tid]    = g_la[tid];
        s_C2[tid]    = g_C2[tid];
    }
    __syncthreads();

    int warp = tid >> 5, lane = tid & 31;
    int row0 = blockIdx.x * 256 + warp * 32;
    if (row0 >= N) return;

    int r  = lane >> 2;        // 0..7
    int cq = (lane & 3) * 2;   // 0,2,4,6

    const float* pbase = x + (size_t)(row0 + r) * DDIM + cq;

    float acc0[8][4], acc1[8][4];
#pragma unroll
    for (int t = 0; t < 8; t++) {
#pragma unroll
        for (int j = 0; j < 4; j++) { acc0[t][j] = 0.0f; acc1[t][j] = 0.0f; }
    }

    // cur[2g+h]: row-group g (rows r + g*8), half h (cols cq / cq+8)
    float2 cur[8];
#pragma unroll
    for (int g = 0; g < 4; g++) {
        cur[2 * g]     = __ldcs(reinterpret_cast<const float2*>(pbase + g * 8 * DDIM));
        cur[2 * g + 1] = __ldcs(reinterpret_cast<const float2*>(pbase + g * 8 * DDIM + 8));
    }

#pragma unroll
    for (int kk = 0; kk < 16; kk++) {
        float2 nxt[8];
#pragma unroll
        for (int i = 0; i < 8; i++) nxt[i] = cur[i];
        if (kk < 15) {
            int off = (kk + 1) * 16;
#pragma unroll
            for (int g = 0; g < 4; g++) {
                nxt[2 * g]     = __ldcs(reinterpret_cast<const float2*>(pbase + g * 8 * DDIM + off));
                nxt[2 * g + 1] = __ldcs(reinterpret_cast<const float2*>(pbase + g * 8 * DDIM + off + 8));
            }
        }
        uint32_t fa[8];
#pragma unroll
        for (int i = 0; i < 8; i++) fa[i] = f22bf(cur[i]);
        int dbase = kk * 16 + cq;
#pragma unroll
        for (int t = 0; t < 8; t++) {
            int n = t * 8 + r;
            uint32_t b0 = *reinterpret_cast<const uint32_t*>(&smu[n][dbase]);
            uint32_t b1 = *reinterpret_cast<const uint32_t*>(&smu[n][dbase + 8]);
            asm volatile(
                "mma.sync.aligned.m16n8k16.row.col.f32.bf16.bf16.f32 "
                "{%0,%1,%2,%3}, {%4,%5,%6,%7}, {%8,%9}, {%0,%1,%2,%3};\n"
                : "+f"(acc0[t][0]), "+f"(acc0[t][1]), "+f"(acc0[t][2]), "+f"(acc0[t][3])
                : "r"(fa[0]), "r"(fa[2]), "r"(fa[1]), "r"(fa[3]), "r"(b0), "r"(b1));
            asm volatile(
                "mma.sync.aligned.m16n8k16.row.col.f32.bf16.bf16.f32 "
                "{%0,%1,%2,%3}, {%4,%5,%6,%7}, {%8,%9}, {%0,%1,%2,%3};\n"
                : "+f"(acc1[t][0]), "+f"(acc1[t][1]), "+f"(acc1[t][2]), "+f"(acc1[t][3])
                : "r"(fa[4]), "r"(fa[6]), "r"(fa[5]), "r"(fa[7]), "r"(b0), "r"(b1));
        }
#pragma unroll
        for (int i = 0; i < 8; i++) cur[i] = nxt[i];
    }

    // ---- epilogue: 4 row-groups (r + g*8); g<2 -> acc0, g>=2 -> acc1; hi half for odd g
#pragma unroll
    for (int g = 0; g < 4; g++) {
        int gr = row0 + r + g * 8;
        int hi = (g & 1) * 2;
        float2* lpout = reinterpret_cast<float2*>(out_lp + (size_t)gr * K_COMP);

        float m = -1e30f;
#pragma unroll
        for (int t = 0; t < 8; t++) {
            float a0 = (g < 2) ? acc0[t][hi] : acc1[t][hi];
            float a1 = (g < 2) ? acc0[t][hi + 1] : acc1[t][hi + 1];
            int c = t * 8 + cq;
            float lp0 = fmaf(s_kappa[c],     a0, s_logC[c]);
            float lp1 = fmaf(s_kappa[c + 1], a1, s_logC[c + 1]);
            __stcs(lpout + (c >> 1), make_float2(lp0, lp1));
            m = fmaxf(m, fmaxf(lp0 + s_la[c], lp1 + s_la[c + 1]));
        }
        m = fmaxf(m, __shfl_xor_sync(0xffffffffu, m, 1));
        m = fmaxf(m, __shfl_xor_sync(0xffffffffu, m, 2));

        float sum = 0.0f;
#pragma unroll
        for (int t = 0; t < 8; t++) {
            float a0 = (g < 2) ? acc0[t][hi] : acc1[t][hi];
            float a1 = (g < 2) ? acc0[t][hi + 1] : acc1[t][hi + 1];
            int c = t * 8 + cq;
            sum += fexp(fmaf(s_kappa[c],     a0, s_C2[c])     - m);
            sum += fexp(fmaf(s_kappa[c + 1], a1, s_C2[c + 1]) - m);
        }
        sum += __shfl_xor_sync(0xffffffffu, sum, 1);
        sum += __shfl_xor_sync(0xffffffffu, sum, 2);

        if ((lane & 3) == 0)
            out_llh[gr] = m + __logf(sum);
    }
}

// ---------------- launch -----------------------------------------------------------
extern "C" void kernel_launch(void* const* d_in, const int* in_sizes, int n_in,
                              void* d_out, int out_size) {
    const float* x           = (const float*)d_in[0];
    const float* alpha_logit = (const float*)d_in[1];
    const float* mu_unnorm   = (const float*)d_in[2];
    const float* log_kappa   = (const float*)d_in[3];

    int K = in_sizes[1];            // 64
    int D = in_sizes[2] / K;        // 256
    int N = in_sizes[0] / D;        // 262144
    (void)K; (void)n_in; (void)out_size;

    float* out = (float*)d_out;
    float* llh = out;               // (N,)
    float* lp  = out + (size_t)N;   // (N, K) row-major

    prep_fast<<<1, 256>>>(alpha_logit, mu_unnorm, log_kappa);
    vmf_main<<<N / 256, 256>>>(x, llh, lp, N);
}

// round 3
// speedup vs baseline: 7.7577x; 1.1619x over previous
#include <cuda_runtime.h>
#include <cuda_bf16.h>
#include <math.h>
#include <stdint.h>

#define K_COMP 64
#define DDIM   256
#define MU_PAD 264   // bf16/row: 132 words -> ldmatrix rows cover all 32 banks

__device__ __align__(16) __nv_bfloat16 g_mu[K_COMP * DDIM];
__device__ float g_kappa[K_COMP];
__device__ float g_logC[K_COMP];
__device__ float g_la[K_COMP];
__device__ float g_C2[K_COMP];

// ---------------- prep: 32 warps, lane-parallel series + warp-reduced softmax ---------
__global__ void prep_fast(const float* __restrict__ alpha_logit,
                          const float* __restrict__ mu_unnorm,
                          const float* __restrict__ log_kappa) {
    __shared__ float cm[K_COMP];   // gammaln(m+1)+gammaln(m+s+1): k-independent
    __shared__ float sa[K_COMP];
    int tid = threadIdx.x, warp = tid >> 5, lane = tid & 31;
    const float s = 0.5f * (float)DDIM - 1.0f;   // 127

    if (tid < K_COMP) {
        cm[tid] = lgammaf((float)tid + 1.0f) + lgammaf((float)tid + s + 1.0f);
        sa[tid] = alpha_logit[tid];
    }
    __syncthreads();

    // log-softmax denominator: lane-parallel over 64 logits, warp-reduced
    float a0 = sa[lane], a1 = sa[lane + 32];
    float amax = fmaxf(a0, a1);
#pragma unroll
    for (int off = 16; off > 0; off >>= 1)
        amax = fmaxf(amax, __shfl_xor_sync(0xffffffffu, amax, off));
    float ae = expf(a0 - amax) + expf(a1 - amax);
#pragma unroll
    for (int off = 16; off > 0; off >>= 1)
        ae += __shfl_xor_sync(0xffffffffu, ae, off);
    float lse_a = amax + logf(ae);

#pragma unroll
    for (int rr = 0; rr < 2; rr++) {
        int k = warp + rr * 32;

        // mu row normalization (lane-parallel over D)
        const float4* p = reinterpret_cast<const float4*>(mu_unnorm + (size_t)k * DDIM);
        float4 v1 = p[lane * 2], v2 = p[lane * 2 + 1];
        float sum = v1.x*v1.x + v1.y*v1.y + v1.z*v1.z + v1.w*v1.w
                  + v2.x*v2.x + v2.y*v2.y + v2.z*v2.z + v2.w*v2.w;
#pragma unroll
        for (int off = 16; off > 0; off >>= 1)
            sum += __shfl_xor_sync(0xffffffffu, sum, off);
        float inv = 1.0f / fmaxf(sqrtf(sum), 1e-12f);
        __nv_bfloat162* dst = reinterpret_cast<__nv_bfloat162*>(g_mu + (size_t)k * DDIM);
        dst[lane * 4 + 0] = __float22bfloat162_rn(make_float2(v1.x * inv, v1.y * inv));
        dst[lane * 4 + 1] = __float22bfloat162_rn(make_float2(v1.z * inv, v1.w * inv));
        dst[lane * 4 + 2] = __float22bfloat162_rn(make_float2(v2.x * inv, v2.y * inv));
        dst[lane * 4 + 3] = __float22bfloat162_rn(make_float2(v2.z * inv, v2.w * inv));

        // log I_s(kappa): lane m and m+32 terms, warp-reduced logsumexp
        float kappa = expf(log_kappa[k]) + 1e-6f;
        float lk2   = logf(0.5f * kappa);
        float t0 = fmaf(2.0f * lane + s,          lk2, -cm[lane]);
        float t1 = fmaf(2.0f * (lane + 32) + s,   lk2, -cm[lane + 32]);
        float tm = fmaxf(t0, t1);
#pragma unroll
        for (int off = 16; off > 0; off >>= 1)
            tm = fmaxf(tm, __shfl_xor_sync(0xffffffffu, tm, off));
        float ts = expf(t0 - tm) + expf(t1 - tm);
#pragma unroll
        for (int off = 16; off > 0; off >>= 1)
            ts += __shfl_xor_sync(0xffffffffu, ts, off);

        if (lane == 0) {
            float lbi  = tm + logf(ts);
            float logC = (float)DDIM * (-0.91893853320467274f) + s * logf(kappa) - lbi;
            float la   = sa[k] - lse_a;
            g_kappa[k] = kappa;
            g_logC[k]  = logC;
            g_la[k]    = la;
            g_C2[k]    = logC + la;
        }
    }
}

// ---------------- fast exp: FFMA-only --------------------------------------------------
__device__ __forceinline__ float fexp(float x) {
    x = fmaxf(x, -87.0f);
    float z = x * 1.4426950408889634f;
    float t = z + 12582912.0f;
    float fi = t - 12582912.0f;
    float f = z - fi;
    int  i  = __float_as_int(t) - 0x4B400000;
    float p = 1.3333558e-3f;
    p = fmaf(p, f, 9.6181291e-3f);
    p = fmaf(p, f, 5.5504109e-2f);
    p = fmaf(p, f, 2.4022651e-1f);
    p = fmaf(p, f, 6.9314718e-1f);
    p = fmaf(p, f, 1.0f);
    return __int_as_float(__float_as_int(p) + (i << 23));
}

__device__ __forceinline__ uint32_t f22bf(float2 v) {
    __nv_bfloat162 b = __float22bfloat162_rn(v);
    return *reinterpret_cast<uint32_t*>(&b);
}

// ---------------- main: 16 rows/warp, ldmatrix B, 2-deep A prefetch -------------------
__global__ void __launch_bounds__(256, 3)
vmf_main(const float* __restrict__ x,
         float* __restrict__ out_llh,
         float* __restrict__ out_lp,
         int N) {
    __shared__ __align__(16) __nv_bfloat16 smu[K_COMP][MU_PAD];
    __shared__ float s_kappa[K_COMP], s_logC[K_COMP], s_la[K_COMP], s_C2[K_COMP];

    int tid = threadIdx.x;

    const uint32_t* gmu32 = reinterpret_cast<const uint32_t*>(g_mu);
    for (int idx = tid; idx < K_COMP * (DDIM / 2); idx += 256) {
        int kk = idx >> 7;
        int dp = idx & 127;
        reinterpret_cast<uint32_t*>(&smu[kk][0])[dp] = gmu32[idx];
    }
    if (tid < K_COMP) {
        s_kappa[tid] = g_kappa[tid];
        s_logC[tid]  = g_logC[tid];
        s_la[tid]    = g_la[tid];
        s_C2[tid]    = g_C2[tid];
    }
    __syncthreads();

    int warp = tid >> 5, lane = tid & 31;
    int row0 = blockIdx.x * 128 + warp * 16;

    int r  = lane >> 2;        // 0..7
    int cq = (lane & 3) * 2;   // 0,2,4,6

    const float* p0 = x + (size_t)(row0 + r) * DDIM + cq;
    const float* p1 = p0 + 8 * DDIM;

    // ldmatrix per-lane address: lanes 0-7 -> tile t b0; 8-15 -> t b1; 16-23 -> t+1 b0; 24-31 -> t+1 b1
    uint32_t smu_base = (uint32_t)__cvta_generic_to_shared(&smu[0][0]);
    int li   = lane & 7;
    int csel = (lane >> 3) & 1;
    int tsel = (lane >> 4) & 1;
    uint32_t lm_base = smu_base + (uint32_t)(((li + tsel * 8) * MU_PAD + csel * 8) * 2);

    float acc[8][4];
#pragma unroll
    for (int t = 0; t < 8; t++)
#pragma unroll
        for (int j = 0; j < 4; j++) acc[t][j] = 0.0f;

    // 2-deep prefetch: 3 rotating buffers of 4 float2
    float2 buf[3][4];
#pragma unroll
    for (int g = 0; g < 2; g++) {
        int off = g * 16;
        buf[g][0] = __ldcs(reinterpret_cast<const float2*>(p0 + off));
        buf[g][1] = __ldcs(reinterpret_cast<const float2*>(p0 + off + 8));
        buf[g][2] = __ldcs(reinterpret_cast<const float2*>(p1 + off));
        buf[g][3] = __ldcs(reinterpret_cast<const float2*>(p1 + off + 8));
    }

#pragma unroll
    for (int kk = 0; kk < 16; kk++) {
        int cs = kk % 3;
        if (kk < 14) {
            int ns = (kk + 2) % 3;
            int off = (kk + 2) * 16;
            buf[ns][0] = __ldcs(reinterpret_cast<const float2*>(p0 + off));
            buf[ns][1] = __ldcs(reinterpret_cast<const float2*>(p0 + off + 8));
            buf[ns][2] = __ldcs(reinterpret_cast<const float2*>(p1 + off));
            buf[ns][3] = __ldcs(reinterpret_cast<const float2*>(p1 + off + 8));
        }
        uint32_t fa0 = f22bf(buf[cs][0]);  // (r,     cq..cq+1)
        uint32_t fa2 = f22bf(buf[cs][1]);  // (r,     cq+8..cq+9)
        uint32_t fa1 = f22bf(buf[cs][2]);  // (r+8,   cq..cq+1)
        uint32_t fa3 = f22bf(buf[cs][3]);  // (r+8,   cq+8..cq+9)

        uint32_t lmaddr = lm_base + (uint32_t)(kk * 32);   // 16 bf16 = 32B per k-step
#pragma unroll
        for (int tp = 0; tp < 4; tp++) {
            uint32_t b0, b1, b2, b3;
            asm volatile(
                "ldmatrix.sync.aligned.m8n8.x4.shared.b16 {%0,%1,%2,%3}, [%4];\n"
                : "=r"(b0), "=r"(b1), "=r"(b2), "=r"(b3)
                : "r"(lmaddr + (uint32_t)(tp * 16 * MU_PAD * 2)));
            asm volatile(
                "mma.sync.aligned.m16n8k16.row.col.f32.bf16.bf16.f32 "
                "{%0,%1,%2,%3}, {%4,%5,%6,%7}, {%8,%9}, {%0,%1,%2,%3};\n"
                : "+f"(acc[tp*2][0]), "+f"(acc[tp*2][1]), "+f"(acc[tp*2][2]), "+f"(acc[tp*2][3])
                : "r"(fa0), "r"(fa1), "r"(fa2), "r"(fa3), "r"(b0), "r"(b1));
            asm volatile(
                "mma.sync.aligned.m16n8k16.row.col.f32.bf16.bf16.f32 "
                "{%0,%1,%2,%3}, {%4,%5,%6,%7}, {%8,%9}, {%0,%1,%2,%3};\n"
                : "+f"(acc[tp*2+1][0]), "+f"(acc[tp*2+1][1]), "+f"(acc[tp*2+1][2]), "+f"(acc[tp*2+1][3])
                : "r"(fa0), "r"(fa1), "r"(fa2), "r"(fa3), "r"(b2), "r"(b3));
        }
    }

    // ---- epilogue: log_prob + per-row logsumexp ----
    int gr0 = row0 + r, gr1 = gr0 + 8;
    float2* lp0 = reinterpret_cast<float2*>(out_lp + (size_t)gr0 * K_COMP);
    float2* lp1 = reinterpret_cast<float2*>(out_lp + (size_t)gr1 * K_COMP);

    float m0 = -1e30f, m1 = -1e30f;
#pragma unroll
    for (int t = 0; t < 8; t++) {
        int c = t * 8 + cq;
        float k0 = s_kappa[c], k1 = s_kappa[c + 1];
        float lc0 = s_logC[c], lc1 = s_logC[c + 1];
        float la0 = s_la[c],   la1 = s_la[c + 1];
        float lp00 = fmaf(k0, acc[t][0], lc0);
        float lp01 = fmaf(k1, acc[t][1], lc1);
        float lp10 = fmaf(k0, acc[t][2], lc0);
        float lp11 = fmaf(k1, acc[t][3], lc1);
        __stcs(lp0 + (c >> 1), make_float2(lp00, lp01));
        __stcs(lp1 + (c >> 1), make_float2(lp10, lp11));
        m0 = fmaxf(m0, fmaxf(lp00 + la0, lp01 + la1));
        m1 = fmaxf(m1, fmaxf(lp10 + la0, lp11 + la1));
    }
    m0 = fmaxf(m0, __shfl_xor_sync(0xffffffffu, m0, 1));
    m0 = fmaxf(m0, __shfl_xor_sync(0xffffffffu, m0, 2));
    m1 = fmaxf(m1, __shfl_xor_sync(0xffffffffu, m1, 1));
    m1 = fmaxf(m1, __shfl_xor_sync(0xffffffffu, m1, 2));

    float s0 = 0.0f, s1 = 0.0f;
#pragma unroll
    for (int t = 0; t < 8; t++) {
        int c = t * 8 + cq;
        float k0 = s_kappa[c], k1 = s_kappa[c + 1];
        float c20 = s_C2[c],   c21 = s_C2[c + 1];
        s0 += fexp(fmaf(k0, acc[t][0], c20) - m0);
        s0 += fexp(fmaf(k1, acc[t][1], c21) - m0);
        s1 += fexp(fmaf(k0, acc[t][2], c20) - m1);
        s1 += fexp(fmaf(k1, acc[t][3], c21) - m1);
    }
    s0 += __shfl_xor_sync(0xffffffffu, s0, 1);
    s0 += __shfl_xor_sync(0xffffffffu, s0, 2);
    s1 += __shfl_xor_sync(0xffffffffu, s1, 1);
    s1 += __shfl_xor_sync(0xffffffffu, s1, 2);

    if ((lane & 3) == 0) {
        out_llh[gr0] = m0 + __logf(s0);
        out_llh[gr1] = m1 + __logf(s1);
    }
}

// ---------------- launch -----------------------------------------------------------
extern "C" void kernel_launch(void* const* d_in, const int* in_sizes, int n_in,
                              void* d_out, int out_size) {
    const float* x           = (const float*)d_in[0];
    const float* alpha_logit = (const float*)d_in[1];
    const float* mu_unnorm   = (const float*)d_in[2];
    const float* log_kappa   = (const float*)d_in[3];

    int K = in_sizes[1];            // 64
    int D = in_sizes[2] / K;        // 256
    int N = in_sizes[0] / D;        // 262144
    (void)K; (void)n_in; (void)out_size;

    float* out = (float*)d_out;
    float* llh = out;               // (N,)
    float* lp  = out + (size_t)N;   // (N, K) row-major

    prep_fast<<<1, 1024>>>(alpha_logit, mu_unnorm, log_kappa);
    vmf_main<<<N / 128, 256>>>(x, llh, lp, N);
}

// round 4
// speedup vs baseline: 8.8735x; 1.1438x over previous
#include <cuda_runtime.h>
#include <cuda_bf16.h>
#include <math.h>
#include <stdint.h>

#define K_COMP 64
#define DDIM   256
#define MU_PAD 264   // bf16/row: 132 words -> ldmatrix rows cover all 32 banks

__device__ __align__(16) __nv_bfloat16 g_mu[K_COMP * DDIM];
__device__ float g_kappa[K_COMP];
__device__ float g_logC[K_COMP];
__device__ float g_la[K_COMP];
__device__ float g_C2[K_COMP];

// ---------------- prep: 32 warps, lane-parallel series + warp-reduced softmax ---------
__global__ void prep_fast(const float* __restrict__ alpha_logit,
                          const float* __restrict__ mu_unnorm,
                          const float* __restrict__ log_kappa) {
    __shared__ float cm[K_COMP];   // gammaln(m+1)+gammaln(m+s+1): k-independent
    __shared__ float sa[K_COMP];
    int tid = threadIdx.x, warp = tid >> 5, lane = tid & 31;
    const float s = 0.5f * (float)DDIM - 1.0f;   // 127

    if (tid < K_COMP) {
        cm[tid] = lgammaf((float)tid + 1.0f) + lgammaf((float)tid + s + 1.0f);
        sa[tid] = alpha_logit[tid];
    }
    __syncthreads();

    float a0 = sa[lane], a1 = sa[lane + 32];
    float amax = fmaxf(a0, a1);
#pragma unroll
    for (int off = 16; off > 0; off >>= 1)
        amax = fmaxf(amax, __shfl_xor_sync(0xffffffffu, amax, off));
    float ae = expf(a0 - amax) + expf(a1 - amax);
#pragma unroll
    for (int off = 16; off > 0; off >>= 1)
        ae += __shfl_xor_sync(0xffffffffu, ae, off);
    float lse_a = amax + logf(ae);

#pragma unroll
    for (int rr = 0; rr < 2; rr++) {
        int k = warp + rr * 32;

        const float4* p = reinterpret_cast<const float4*>(mu_unnorm + (size_t)k * DDIM);
        float4 v1 = p[lane * 2], v2 = p[lane * 2 + 1];
        float sum = v1.x*v1.x + v1.y*v1.y + v1.z*v1.z + v1.w*v1.w
                  + v2.x*v2.x + v2.y*v2.y + v2.z*v2.z + v2.w*v2.w;
#pragma unroll
        for (int off = 16; off > 0; off >>= 1)
            sum += __shfl_xor_sync(0xffffffffu, sum, off);
        float inv = 1.0f / fmaxf(sqrtf(sum), 1e-12f);
        __nv_bfloat162* dst = reinterpret_cast<__nv_bfloat162*>(g_mu + (size_t)k * DDIM);
        dst[lane * 4 + 0] = __float22bfloat162_rn(make_float2(v1.x * inv, v1.y * inv));
        dst[lane * 4 + 1] = __float22bfloat162_rn(make_float2(v1.z * inv, v1.w * inv));
        dst[lane * 4 + 2] = __float22bfloat162_rn(make_float2(v2.x * inv, v2.y * inv));
        dst[lane * 4 + 3] = __float22bfloat162_rn(make_float2(v2.z * inv, v2.w * inv));

        float kappa = expf(log_kappa[k]) + 1e-6f;
        float lk2   = logf(0.5f * kappa);
        float t0 = fmaf(2.0f * lane + s,        lk2, -cm[lane]);
        float t1 = fmaf(2.0f * (lane + 32) + s, lk2, -cm[lane + 32]);
        float tm = fmaxf(t0, t1);
#pragma unroll
        for (int off = 16; off > 0; off >>= 1)
            tm = fmaxf(tm, __shfl_xor_sync(0xffffffffu, tm, off));
        float ts = expf(t0 - tm) + expf(t1 - tm);
#pragma unroll
        for (int off = 16; off > 0; off >>= 1)
            ts += __shfl_xor_sync(0xffffffffu, ts, off);

        if (lane == 0) {
            float lbi  = tm + logf(ts);
            float logC = (float)DDIM * (-0.91893853320467274f) + s * logf(kappa) - lbi;
            float la   = sa[k] - lse_a;
            g_kappa[k] = kappa;
            g_logC[k]  = logC;
            g_la[k]    = la;
            g_C2[k]    = logC + la;
        }
    }
}

// ---------------- fast exp: FFMA-only --------------------------------------------------
__device__ __forceinline__ float fexp(float x) {
    x = fmaxf(x, -87.0f);
    float z = x * 1.4426950408889634f;
    float t = z + 12582912.0f;
    float fi = t - 12582912.0f;
    float f = z - fi;
    int  i  = __float_as_int(t) - 0x4B400000;
    float p = 1.3333558e-3f;
    p = fmaf(p, f, 9.6181291e-3f);
    p = fmaf(p, f, 5.5504109e-2f);
    p = fmaf(p, f, 2.4022651e-1f);
    p = fmaf(p, f, 6.9314718e-1f);
    p = fmaf(p, f, 1.0f);
    return __int_as_float(__float_as_int(p) + (i << 23));
}

__device__ __forceinline__ uint32_t f22bf(float2 v) {
    __nv_bfloat162 b = __float22bfloat162_rn(v);
    return *reinterpret_cast<uint32_t*>(&b);
}

// ---------------- main: permuted-k layout -> A loads are contiguous LDG.128 -----------
// k-pair permutation per 16-col chunk: smem slot i holds physical pair (i<4 ? 2i : 2i-7).
// Lane c's float4 (phys pairs 2c, 2c+1) then equals logical pairs (c, c+4) = exact
// m16n8k16 A fragment. ldmatrix on permuted smem keeps B consistent. Dot product is
// permutation-invariant in k, so results are bit-identical.
__global__ void __launch_bounds__(256, 3)
vmf_main(const float* __restrict__ x,
         float* __restrict__ out_llh,
         float* __restrict__ out_lp,
         int N) {
    __shared__ __align__(16) __nv_bfloat16 smu[K_COMP][MU_PAD];
    __shared__ float s_kappa[K_COMP], s_logC[K_COMP], s_la[K_COMP], s_C2[K_COMP];

    int tid = threadIdx.x;

    // stage mu with k-pair permutation (word = bf16 pair granularity)
    const uint32_t* gmu32 = reinterpret_cast<const uint32_t*>(g_mu);
    for (int idx = tid; idx < K_COMP * (DDIM / 2); idx += 256) {
        int kk = idx >> 7;          // component
        int dp = idx & 127;         // dest word slot
        int i  = dp & 7;            // slot within 16-col chunk
        int srcp = (i < 4) ? (2 * i) : (2 * i - 7);
        int src  = (dp & ~7) | srcp;
        reinterpret_cast<uint32_t*>(&smu[kk][0])[dp] = gmu32[kk * 128 + src];
    }
    if (tid < K_COMP) {
        s_kappa[tid] = g_kappa[tid];
        s_logC[tid]  = g_logC[tid];
        s_la[tid]    = g_la[tid];
        s_C2[tid]    = g_C2[tid];
    }
    __syncthreads();

    int warp = tid >> 5, lane = tid & 31;
    int row0 = blockIdx.x * 128 + warp * 16;

    int r  = lane >> 2;        // 0..7
    int cq = (lane & 3) * 2;   // logical col-pair base (epilogue)

    const float* p0 = x + (size_t)(row0 + r) * DDIM + (lane & 3) * 4;
    const float* p1 = p0 + 8 * DDIM;

    // ldmatrix B lane address (as R3; reads permuted smem)
    uint32_t smu_base = (uint32_t)__cvta_generic_to_shared(&smu[0][0]);
    int li   = lane & 7;
    int csel = (lane >> 3) & 1;
    int tsel = (lane >> 4) & 1;
    uint32_t lm_base = smu_base + (uint32_t)(((li + tsel * 8) * MU_PAD + csel * 8) * 2);

    float acc[8][4];
#pragma unroll
    for (int t = 0; t < 8; t++)
#pragma unroll
        for (int j = 0; j < 4; j++) acc[t][j] = 0.0f;

    // depth-2 prefetch, 3 rotating buffers of 2 float4
    float4 buf[3][2];
#pragma unroll
    for (int g = 0; g < 2; g++) {
        buf[g][0] = __ldcs(reinterpret_cast<const float4*>(p0 + g * 16));
        buf[g][1] = __ldcs(reinterpret_cast<const float4*>(p1 + g * 16));
    }

#pragma unroll
    for (int kk = 0; kk < 16; kk++) {
        int cs = kk % 3;
        if (kk < 14) {
            int ns = (kk + 2) % 3;
            int off = (kk + 2) * 16;
            buf[ns][0] = __ldcs(reinterpret_cast<const float4*>(p0 + off));
            buf[ns][1] = __ldcs(reinterpret_cast<const float4*>(p1 + off));
        }
        float4 A0 = buf[cs][0], A1 = buf[cs][1];
        uint32_t fa0 = f22bf(make_float2(A0.x, A0.y));   // row r,   logical pair c
        uint32_t fa2 = f22bf(make_float2(A0.z, A0.w));   // row r,   logical pair c+4
        uint32_t fa1 = f22bf(make_float2(A1.x, A1.y));   // row r+8, logical pair c
        uint32_t fa3 = f22bf(make_float2(A1.z, A1.w));   // row r+8, logical pair c+4

        uint32_t lmaddr = lm_base + (uint32_t)(kk * 32);
#pragma unroll
        for (int tp = 0; tp < 4; tp++) {
            uint32_t b0, b1, b2, b3;
            asm volatile(
                "ldmatrix.sync.aligned.m8n8.x4.shared.b16 {%0,%1,%2,%3}, [%4];\n"
                : "=r"(b0), "=r"(b1), "=r"(b2), "=r"(b3)
                : "r"(lmaddr + (uint32_t)(tp * 16 * MU_PAD * 2)));
            asm volatile(
                "mma.sync.aligned.m16n8k16.row.col.f32.bf16.bf16.f32 "
                "{%0,%1,%2,%3}, {%4,%5,%6,%7}, {%8,%9}, {%0,%1,%2,%3};\n"
                : "+f"(acc[tp*2][0]), "+f"(acc[tp*2][1]), "+f"(acc[tp*2][2]), "+f"(acc[tp*2][3])
                : "r"(fa0), "r"(fa1), "r"(fa2), "r"(fa3), "r"(b0), "r"(b1));
            asm volatile(
                "mma.sync.aligned.m16n8k16.row.col.f32.bf16.bf16.f32 "
                "{%0,%1,%2,%3}, {%4,%5,%6,%7}, {%8,%9}, {%0,%1,%2,%3};\n"
                : "+f"(acc[tp*2+1][0]), "+f"(acc[tp*2+1][1]), "+f"(acc[tp*2+1][2]), "+f"(acc[tp*2+1][3])
                : "r"(fa0), "r"(fa1), "r"(fa2), "r"(fa3), "r"(b2), "r"(b3));
        }
    }

    // ---- epilogue: log_prob + per-row logsumexp (unchanged; logical cols) ----
    int gr0 = row0 + r, gr1 = gr0 + 8;
    float2* lp0 = reinterpret_cast<float2*>(out_lp + (size_t)gr0 * K_COMP);
    float2* lp1 = reinterpret_cast<float2*>(out_lp + (size_t)gr1 * K_COMP);

    float m0 = -1e30f, m1 = -1e30f;
#pragma unroll
    for (int t = 0; t < 8; t++) {
        int c = t * 8 + cq;
        float k0 = s_kappa[c], k1 = s_kappa[c + 1];
        float lc0 = s_logC[c], lc1 = s_logC[c + 1];
        float la0 = s_la[c],   la1 = s_la[c + 1];
        float lp00 = fmaf(k0, acc[t][0], lc0);
        float lp01 = fmaf(k1, acc[t][1], lc1);
        float lp10 = fmaf(k0, acc[t][2], lc0);
        float lp11 = fmaf(k1, acc[t][3], lc1);
        __stcs(lp0 + (c >> 1), make_float2(lp00, lp01));
        __stcs(lp1 + (c >> 1), make_float2(lp10, lp11));
        m0 = fmaxf(m0, fmaxf(lp00 + la0, lp01 + la1));
        m1 = fmaxf(m1, fmaxf(lp10 + la0, lp11 + la1));
    }
    m0 = fmaxf(m0, __shfl_xor_sync(0xffffffffu, m0, 1));
    m0 = fmaxf(m0, __shfl_xor_sync(0xffffffffu, m0, 2));
    m1 = fmaxf(m1, __shfl_xor_sync(0xffffffffu, m1, 1));
    m1 = fmaxf(m1, __shfl_xor_sync(0xffffffffu, m1, 2));

    float s0 = 0.0f, s1 = 0.0f;
#pragma unroll
    for (int t = 0; t < 8; t++) {
        int c = t * 8 + cq;
        float k0 = s_kappa[c], k1 = s_kappa[c + 1];
        float c20 = s_C2[c],   c21 = s_C2[c + 1];
        s0 += fexp(fmaf(k0, acc[t][0], c20) - m0);
        s0 += fexp(fmaf(k1, acc[t][1], c21) - m0);
        s1 += fexp(fmaf(k0, acc[t][2], c20) - m1);
        s1 += fexp(fmaf(k1, acc[t][3], c21) - m1);
    }
    s0 += __shfl_xor_sync(0xffffffffu, s0, 1);
    s0 += __shfl_xor_sync(0xffffffffu, s0, 2);
    s1 += __shfl_xor_sync(0xffffffffu, s1, 1);
    s1 += __shfl_xor_sync(0xffffffffu, s1, 2);

    if ((lane & 3) == 0) {
        out_llh[gr0] = m0 + __logf(s0);
        out_llh[gr1] = m1 + __logf(s1);
    }
}

// ---------------- launch -----------------------------------------------------------
extern "C" void kernel_launch(void* const* d_in, const int* in_sizes, int n_in,
                              void* d_out, int out_size) {
    const float* x           = (const float*)d_in[0];
    const float* alpha_logit = (const float*)d_in[1];
    const float* mu_unnorm   = (const float*)d_in[2];
    const float* log_kappa   = (const float*)d_in[3];

    int K = in_sizes[1];            // 64
    int D = in_sizes[2] / K;        // 256
    int N = in_sizes[0] / D;        // 262144
    (void)K; (void)n_in; (void)out_size;

    float* out = (float*)d_out;
    float* llh = out;               // (N,)
    float* lp  = out + (size_t)N;   // (N, K) row-major

    prep_fast<<<1, 1024>>>(alpha_logit, mu_unnorm, log_kappa);
    vmf_main<<<N / 128, 256>>>(x, llh, lp, N);
}